// round 12
// baseline (speedup 1.0000x reference)
#include <cuda_runtime.h>
#include <cuda_bf16.h>

// Problem constants (fixed by setup_inputs)
#define NN 256   // num_nodes
#define PP 5     // num_pieces
#define HH 32    // hidden_dim
#define BB 256   // batch

typedef unsigned long long ull;

// __device__ scratch (no runtime allocation allowed)
// Pair-interleaved packed x: g_xw2[(j>>1)*2*BB + b*2 + (j&1)]
//   = x[b][j] bits with the 3 mantissa LSBs replaced by the segment index
//     s = #{k : x > bp_k} (0..5). Perturbation <= 7 ulp (~8e-7 relative).
__device__ unsigned g_xw2[NN * BB];
__device__ float    g_adjT[NN * NN];  // adjT[i][j] = adjacency[j][i]

#define PACK2(d, lo, hi) \
    asm("mov.b64 %0, {%1, %2};" : "=l"(d) : "r"(lo), "r"(hi))
#define UNPACK2(lo, hi, s) \
    asm("mov.b64 {%0, %1}, %2;" : "=r"(lo), "=r"(hi) : "l"(s))
#define FMA2(d, a, b, c) \
    asm("fma.rn.f32x2 %0, %1, %2, %3;" : "=l"(d) : "l"(a), "l"(b), "l"(c))
#define ADD2(d, a, b) \
    asm("add.rn.f32x2 %0, %1, %2;" : "=l"(d) : "l"(a), "l"(b))

// Dynamic shared memory layout (static __shared__ is capped at 48 KB; our
// 51,264 B footprint requires the dynamic path + MaxDynamicSharedMemorySize):
//   [0, 49152)        ulonglong2 tab[2][NN*6]   (pair 1 at +TABBYTES)
//   [49152, 51200)    float4     mlp[4][HH]
//   [51200, 51264)    float      red[16]        (red[ii*4 + warp])
#define TABBYTES  (NN * 6 * 16)            // one i-pair table: 24576 bytes
#define MLP_OFF   (2 * TABBYTES)           // 49152
#define RED_OFF   (MLP_OFF + 4 * HH * 16)  // 51200
#define SMEM_TOTAL (RED_OFF + 16 * 4)      // 51264

// ---------------------------------------------------------------------------
// Kernel 0: transpose adjacency; transpose x while fusing the segment index
// (bp is a shared sorted linspace broadcast) into x's 3 mantissa LSBs.
// grid (8,8,2), block (32,8)
// ---------------------------------------------------------------------------
__global__ void prep_kernel(const float* __restrict__ x,
                            const float* __restrict__ adj,
                            const float* __restrict__ bp) {
    __shared__ float tile[32][33];
    const bool isadj = (blockIdx.z != 0);
    const float* src = isadj ? adj : x;
    const int bx = blockIdx.x * 32;
    const int by = blockIdx.y * 32;
    const int tx = threadIdx.x;
    const int ty = threadIdx.y;
#pragma unroll
    for (int r = 0; r < 32; r += 8)
        tile[ty + r][tx] = src[(by + ty + r) * NN + (bx + tx)];
    __syncthreads();
    if (isadj) {
#pragma unroll
        for (int r = 0; r < 32; r += 8)
            g_adjT[(bx + ty + r) * NN + (by + tx)] = tile[tx][ty + r];
    } else {
        const float b0 = __ldg(bp + 0), b1 = __ldg(bp + 1), b2 = __ldg(bp + 2),
                    b3 = __ldg(bp + 3), b4 = __ldg(bp + 4);
#pragma unroll
        for (int r = 0; r < 32; r += 8) {
            const float xv = tile[tx][ty + r];
            const unsigned s =
                (xv > b0) + (xv > b1) + (xv > b2) + (xv > b3) + (xv > b4);
            const unsigned w = (__float_as_uint(xv) & ~7u) | s;
            const int j = bx + ty + r;     // source node
            const int b = by + tx;         // batch element
            g_xw2[(j >> 1) * (2 * BB) + b * 2 + (j & 1)] = w;
        }
    }
}

// ---------------------------------------------------------------------------
// Kernel 1: segment-table contraction, 4 target nodes per block, f32x2 math,
// fused per-node MLP.
// grid = 128 : blockIdx.x = (i_quad << 1) | b_half ; block = 128 threads.
//
// contribution[b,i] = sum_j ( S[i,j,s(b,j)] * x[b,j] + T[i,j,s(b,j)] ) + base_i
//   S[i,j,s] = sum_{k<s} ew*w_pw[i,j,k],  T[i,j,s] = -sum_{k<s} ew*w_pw[i,j,k]*bp_k
// ---------------------------------------------------------------------------
__global__ __launch_bounds__(128, 2)
void pwlseg_kernel(const float* __restrict__ bp,
                   const float* __restrict__ w_pw,
                   const float* __restrict__ b_pw,
                   const float* __restrict__ W1,
                   const float* __restrict__ b1,
                   const float* __restrict__ W2,
                   const float* __restrict__ b2,
                   float* __restrict__ out) {
    extern __shared__ char smem_raw[];
    char*   tA  = smem_raw;                            // tab, pair 1 at +TABBYTES
    float4* mlp = (float4*)(smem_raw + MLP_OFF);       // mlp[ii*HH + h]
    float*  red = (float*)(smem_raw + RED_OFF);        // red[ii*4 + warp]

    const int i0    = (blockIdx.x >> 1) * 4;   // target nodes i0..i0+3
    const int bbase = (blockIdx.x & 1) * 128;  // batch half
    const int t     = threadIdx.x;

    // ------------- staging: 128 threads stage 256 source nodes --------------
    {
        const float bpv[PP] = {__ldg(bp + 0), __ldg(bp + 1), __ldg(bp + 2),
                               __ldg(bp + 3), __ldg(bp + 4)};
        float part[4] = {0.f, 0.f, 0.f, 0.f};
        for (int j = t; j < NN; j += 128) {
#pragma unroll
            for (int ii = 0; ii < 4; ii++) {
                const int i = i0 + ii;
                const float a = g_adjT[i * NN + j];
                const float ew = (a > 0.01f && j != i) ? a : 0.0f;
                const float* wp = w_pw + (size_t)(i * NN + j) * PP;
                float S[6], T[6];
                float cs = 0.0f, ct = 0.0f;
                S[0] = 0.0f; T[0] = 0.0f;
#pragma unroll
                for (int k = 0; k < PP; k++) {
                    const float w = ew * wp[k];
                    cs += w;
                    ct = fmaf(-w, bpv[k], ct);
                    S[k + 1] = cs;
                    T[k + 1] = ct;
                }
                part[ii] = fmaf(ew, b_pw[i * NN + j], part[ii]);
                const int p = ii >> 1, lane = ii & 1;
                float* e = (float*)(tA + p * TABBYTES + j * 96);
#pragma unroll
                for (int s = 0; s < 6; s++) {
                    e[s * 4 + lane]     = S[s];   // S slot
                    e[s * 4 + 2 + lane] = T[s];   // T slot
                }
            }
        }
        // base_i = sum_j ew * b_pw[i,j]  (batch-independent)
#pragma unroll
        for (int ii = 0; ii < 4; ii++) {
            float p = part[ii];
#pragma unroll
            for (int off = 16; off; off >>= 1)
                p += __shfl_xor_sync(0xffffffffu, p, off);
            if ((t & 31) == 0) red[ii * 4 + (t >> 5)] = p;
        }
        if (t < 4 * HH) {
            const int ii = t >> 5, h = t & 31, i = i0 + ii;
            mlp[ii * HH + h] = make_float4(W1[i * HH + h], b1[i * HH + h],
                                           W2[(i * 2 + 0) * HH + h],
                                           W2[(i * 2 + 1) * HH + h]);
        }
    }
    __syncthreads();

    // ------------- main loop: b = bbase + t, stream packed x over j ----------
    // One LDG.64 fetches the packed-x pair for (j, j+1); the table offset is
    // (w & 7) << 4 -> LOP3 + LEA (shift folded into the add). Unroll 16
    // front-batches 16 independent LDG.64s (MLP_eff ~ 16) to cover L2 latency.
    const uint2* xp = (const uint2*)&g_xw2[(bbase + t) * 2];
    ull aS0 = 0ull, aT0 = 0ull, aS1 = 0ull, aT1 = 0ull;   // pair 0 (even/odd j)
    ull bS0 = 0ull, bT0 = 0ull, bS1 = 0ull, bT1 = 0ull;   // pair 1 (even/odd j)

#pragma unroll 16
    for (int jp = 0; jp < NN / 2; jp++) {
        const uint2 w = __ldg(xp + jp * BB);             // coalesced LDG.64
        ull x0, x1;
        PACK2(x0, w.x, w.x);
        PACK2(x1, w.y, w.y);
        const char* p0 = tA + (2 * jp + 0) * 96 + (int)((w.x & 7u) << 4);
        const char* p1 = tA + (2 * jp + 1) * 96 + (int)((w.y & 7u) << 4);
        const ulonglong2 eA0 = *(const ulonglong2*)(p0);             // LDS.128
        const ulonglong2 eB0 = *(const ulonglong2*)(p0 + TABBYTES);  // +imm
        const ulonglong2 eA1 = *(const ulonglong2*)(p1);
        const ulonglong2 eB1 = *(const ulonglong2*)(p1 + TABBYTES);
        FMA2(aS0, eA0.x, x0, aS0);  ADD2(aT0, aT0, eA0.y);
        FMA2(bS0, eB0.x, x0, bS0);  ADD2(bT0, bT0, eB0.y);
        FMA2(aS1, eA1.x, x1, aS1);  ADD2(aT1, aT1, eA1.y);
        FMA2(bS1, eB1.x, x1, bS1);  ADD2(bT1, bT1, eB1.y);
    }

    ull aS, aT, bS, bT;
    ADD2(aS, aS0, aS1);  ADD2(aT, aT0, aT1);
    ADD2(bS, bS0, bS1);  ADD2(bT, bT0, bT1);

    unsigned u0, u1, u2, u3, v0, v1, v2, v3;
    UNPACK2(u0, u1, aS);  UNPACK2(v0, v1, aT);
    UNPACK2(u2, u3, bS);  UNPACK2(v2, v3, bT);

    float c[4];
    c[0] = __uint_as_float(u0) + __uint_as_float(v0);
    c[1] = __uint_as_float(u1) + __uint_as_float(v1);
    c[2] = __uint_as_float(u2) + __uint_as_float(v2);
    c[3] = __uint_as_float(u3) + __uint_as_float(v3);
#pragma unroll
    for (int ii = 0; ii < 4; ii++)
        c[ii] += (red[ii * 4 + 0] + red[ii * 4 + 1]) +
                 (red[ii * 4 + 2] + red[ii * 4 + 3]);

    // ------------- per-node MLP: Linear(1,H) -> ReLU -> Linear(H,2) ----------
    // b2 for the 4 nodes: 8 contiguous floats -> two float4 loads.
    const float4 b2lo = __ldg((const float4*)&b2[i0 * 2]);      // m0,s0,m1,s1
    const float4 b2hi = __ldg((const float4*)&b2[i0 * 2 + 4]);  // m2,s2,m3,s3
    float m[4] = {b2lo.x, b2lo.z, b2hi.x, b2hi.z};
    float s[4] = {b2lo.y, b2lo.w, b2hi.y, b2hi.w};
#pragma unroll
    for (int ii = 0; ii < 4; ii++) {
#pragma unroll
        for (int h = 0; h < HH; h++) {
            const float4 q = mlp[ii * HH + h];
            const float hv = fmaxf(fmaf(c[ii], q.x, q.y), 0.f);
            m[ii] = fmaf(hv, q.z, m[ii]);
            s[ii] = fmaf(hv, q.w, s[ii]);
        }
    }

    // output: means (B,N) then log_stds (B,N); i0 % 4 == 0 -> STG.128 x2
    const int b = bbase + t;
    *(float4*)&out[b * NN + i0]           = make_float4(m[0], m[1], m[2], m[3]);
    *(float4*)&out[BB * NN + b * NN + i0] = make_float4(s[0], s[1], s[2], s[3]);
}

// ---------------------------------------------------------------------------
extern "C" void kernel_launch(void* const* d_in, const int* in_sizes, int n_in,
                              void* d_out, int out_size) {
    const float* x    = (const float*)d_in[0];
    const float* adj  = (const float*)d_in[1];
    const float* bp   = (const float*)d_in[2];
    const float* w_pw = (const float*)d_in[3];
    const float* b_pw = (const float*)d_in[4];
    const float* W1   = (const float*)d_in[5];
    const float* b1   = (const float*)d_in[6];
    const float* W2   = (const float*)d_in[7];
    const float* b2   = (const float*)d_in[8];
    float* out = (float*)d_out;

    // Opt in to >48 KB dynamic shared memory (idempotent, host-side, not a
    // stream op -> not captured; allocates nothing).
    cudaFuncSetAttribute(pwlseg_kernel,
                         cudaFuncAttributeMaxDynamicSharedMemorySize,
                         SMEM_TOTAL);

    dim3 tgrid(8, 8, 2), tblk(32, 8);
    prep_kernel<<<tgrid, tblk>>>(x, adj, bp);

    pwlseg_kernel<<<128, 128, SMEM_TOTAL>>>(bp, w_pw, b_pw, W1, b1, W2, b2, out);
}

// round 14
// speedup vs baseline: 1.0453x; 1.0453x over previous
#include <cuda_runtime.h>
#include <cuda_bf16.h>

// Problem constants (fixed by setup_inputs)
#define NN 256   // num_nodes
#define PP 5     // num_pieces
#define HH 32    // hidden_dim
#define BB 256   // batch

typedef unsigned long long ull;

// __device__ scratch (no runtime allocation allowed)
// Pair-interleaved packed x: g_xw2[(j>>1)*2*BB + b*2 + (j&1)]
//   = x[b][j] bits with the 3 mantissa LSBs replaced by the segment index
//     s = #{k : x > bp_k} (0..5). Perturbation <= 7 ulp (~8e-7 relative).
__device__ unsigned g_xw2[NN * BB];
__device__ float    g_adjT[NN * NN];  // adjT[i][j] = adjacency[j][i]

#define PACK2(d, lo, hi) \
    asm("mov.b64 %0, {%1, %2};" : "=l"(d) : "r"(lo), "r"(hi))
#define UNPACK2(lo, hi, s) \
    asm("mov.b64 {%0, %1}, %2;" : "=r"(lo), "=r"(hi) : "l"(s))
#define FMA2(d, a, b, c) \
    asm("fma.rn.f32x2 %0, %1, %2, %3;" : "=l"(d) : "l"(a), "l"(b), "l"(c))
#define ADD2(d, a, b) \
    asm("add.rn.f32x2 %0, %1, %2;" : "=l"(d) : "l"(a), "l"(b))

// Dynamic shared memory layout (static __shared__ capped at 48 KB):
//   [0, 49152)        ulonglong2 tab[2][NN*6]   (pair 1 at +TABBYTES)
//   [49152, 51200)    float4     mlp[4][HH]
//   [51200, 51328)    float      red2[4][8]     (per-warp base partials)
//   [51328, 59520)    float      redc[4][4][128] (jq, ii, b partial sums;
//                                 reused as m/s staging for coalesced stores)
#define TABBYTES  (NN * 6 * 16)            // one i-pair table: 24576 bytes
#define MLP_OFF   (2 * TABBYTES)           // 49152
#define RED2_OFF  (MLP_OFF + 4 * HH * 16)  // 51200
#define REDC_OFF  (RED2_OFF + 128)         // 51328
#define SMEM_TOTAL (REDC_OFF + 4 * 4 * 128 * 4)  // 59520

// ---------------------------------------------------------------------------
// Kernel 0: transpose adjacency; transpose x while fusing the segment index
// (bp is a shared sorted linspace broadcast) into x's 3 mantissa LSBs.
// grid (8,8,2), block (32,8)
// ---------------------------------------------------------------------------
__global__ void prep_kernel(const float* __restrict__ x,
                            const float* __restrict__ adj,
                            const float* __restrict__ bp) {
    __shared__ float tile[32][33];
    const bool isadj = (blockIdx.z != 0);
    const float* src = isadj ? adj : x;
    const int bx = blockIdx.x * 32;
    const int by = blockIdx.y * 32;
    const int tx = threadIdx.x;
    const int ty = threadIdx.y;
#pragma unroll
    for (int r = 0; r < 32; r += 8)
        tile[ty + r][tx] = src[(by + ty + r) * NN + (bx + tx)];
    __syncthreads();
    if (isadj) {
#pragma unroll
        for (int r = 0; r < 32; r += 8)
            g_adjT[(bx + ty + r) * NN + (by + tx)] = tile[tx][ty + r];
    } else {
        const float b0 = __ldg(bp + 0), b1 = __ldg(bp + 1), b2 = __ldg(bp + 2),
                    b3 = __ldg(bp + 3), b4 = __ldg(bp + 4);
#pragma unroll
        for (int r = 0; r < 32; r += 8) {
            const float xv = tile[tx][ty + r];
            const unsigned s =
                (xv > b0) + (xv > b1) + (xv > b2) + (xv > b3) + (xv > b4);
            const unsigned w = (__float_as_uint(xv) & ~7u) | s;
            const int j = bx + ty + r;     // source node
            const int b = by + tx;         // batch element
            g_xw2[(j >> 1) * (2 * BB) + b * 2 + (j & 1)] = w;
        }
    }
}

// ---------------------------------------------------------------------------
// Kernel 1: segment-table contraction, 4 target nodes per block, the j-range
// split across 4 warp-groups (512 threads -> 16 warps/SM vs round-11's 4),
// f32x2 math, smem combine, fully-parallel fused per-node MLP tail.
// grid = 128 : blockIdx.x = (i_quad << 1) | b_half.
//
// contribution[b,i] = sum_j ( S[i,j,s(b,j)] * x[b,j] + T[i,j,s(b,j)] ) + base_i
//   S[i,j,s] = sum_{k<s} ew*w_pw[i,j,k],  T[i,j,s] = -sum_{k<s} ew*w_pw[i,j,k]*bp_k
// ---------------------------------------------------------------------------
__global__ __launch_bounds__(512, 1)
void pwlseg_kernel(const float* __restrict__ bp,
                   const float* __restrict__ w_pw,
                   const float* __restrict__ b_pw,
                   const float* __restrict__ W1,
                   const float* __restrict__ b1,
                   const float* __restrict__ W2,
                   const float* __restrict__ b2,
                   float* __restrict__ out) {
    extern __shared__ char smem_raw[];
    char*   tA   = smem_raw;                        // tab, pair 1 at +TABBYTES
    float4* mlp  = (float4*)(smem_raw + MLP_OFF);   // mlp[ii*HH + h]
    float*  red2 = (float*)(smem_raw + RED2_OFF);   // red2[ii*8 + warp]
    float*  redc = (float*)(smem_raw + REDC_OFF);   // redc[(jq*4+ii)*128 + b]

    const int i0    = (blockIdx.x >> 1) * 4;   // target nodes i0..i0+3
    const int bbase = (blockIdx.x & 1) * 128;  // batch half
    const int t     = threadIdx.x;

    // ------------- staging: 512 threads stage 2x(256 j x 2 i) ---------------
    {
        const float bpv[PP] = {__ldg(bp + 0), __ldg(bp + 1), __ldg(bp + 2),
                               __ldg(bp + 3), __ldg(bp + 4)};
        const int sj  = t & 255;   // source node this thread stages
        const int grp = t >> 8;    // i-pair (0: i0/i0+1, 1: i0+2/i0+3)
        float pp[2];
#pragma unroll
        for (int lane = 0; lane < 2; lane++) {
            const int i = i0 + grp * 2 + lane;
            const float a = g_adjT[i * NN + sj];
            const float ew = (a > 0.01f && sj != i) ? a : 0.0f;
            const float* wp = w_pw + (size_t)(i * NN + sj) * PP;
            float S[6], T[6];
            float cs = 0.0f, ct = 0.0f;
            S[0] = 0.0f; T[0] = 0.0f;
#pragma unroll
            for (int k = 0; k < PP; k++) {
                const float w = ew * wp[k];
                cs += w;
                ct = fmaf(-w, bpv[k], ct);
                S[k + 1] = cs;
                T[k + 1] = ct;
            }
            pp[lane] = ew * b_pw[i * NN + sj];
            float* e = (float*)(tA + grp * TABBYTES + sj * 96);
#pragma unroll
            for (int s = 0; s < 6; s++) {
                e[s * 4 + lane]     = S[s];   // S slot
                e[s * 4 + 2 + lane] = T[s];   // T slot
            }
        }
        // base partials: warp-reduce, one slot per warp (8 warps per pair)
#pragma unroll
        for (int off = 16; off; off >>= 1) {
            pp[0] += __shfl_xor_sync(0xffffffffu, pp[0], off);
            pp[1] += __shfl_xor_sync(0xffffffffu, pp[1], off);
        }
        if ((t & 31) == 0) {
            const int w = (t >> 5) & 7;
            red2[(grp * 2 + 0) * 8 + w] = pp[0];
            red2[(grp * 2 + 1) * 8 + w] = pp[1];
        }
        if (t < 4 * HH) {
            const int ii = t >> 5, h = t & 31, i = i0 + ii;
            mlp[ii * HH + h] = make_float4(W1[i * HH + h], b1[i * HH + h],
                                           W2[(i * 2 + 0) * HH + h],
                                           W2[(i * 2 + 1) * HH + h]);
        }
    }
    __syncthreads();

    // ------------- main loop: thread = (jq, b); 32 j-pairs each -------------
    const int jq = t >> 7;            // j-quarter 0..3
    const int tb = t & 127;           // batch lane within half
    const uint2* xp = (const uint2*)&g_xw2[(bbase + tb) * 2];
    ull aS0 = 0ull, aT0 = 0ull, aS1 = 0ull, aT1 = 0ull;   // pair 0 (even/odd j)
    ull bS0 = 0ull, bT0 = 0ull, bS1 = 0ull, bT1 = 0ull;   // pair 1 (even/odd j)

    const int jp0 = jq * 32;
#pragma unroll 8
    for (int q = 0; q < 32; q++) {
        const int jp = jp0 + q;
        const uint2 w = __ldg(xp + jp * BB);             // coalesced LDG.64
        ull x0, x1;
        PACK2(x0, w.x, w.x);
        PACK2(x1, w.y, w.y);
        const char* p0 = tA + (2 * jp + 0) * 96 + (int)((w.x & 7u) << 4);
        const char* p1 = tA + (2 * jp + 1) * 96 + (int)((w.y & 7u) << 4);
        const ulonglong2 eA0 = *(const ulonglong2*)(p0);             // LDS.128
        const ulonglong2 eB0 = *(const ulonglong2*)(p0 + TABBYTES);  // +imm
        const ulonglong2 eA1 = *(const ulonglong2*)(p1);
        const ulonglong2 eB1 = *(const ulonglong2*)(p1 + TABBYTES);
        FMA2(aS0, eA0.x, x0, aS0);  ADD2(aT0, aT0, eA0.y);
        FMA2(bS0, eB0.x, x0, bS0);  ADD2(bT0, bT0, eB0.y);
        FMA2(aS1, eA1.x, x1, aS1);  ADD2(aT1, aT1, eA1.y);
        FMA2(bS1, eB1.x, x1, bS1);  ADD2(bT1, bT1, eB1.y);
    }

    ull aS, aT, bS, bT;
    ADD2(aS, aS0, aS1);  ADD2(aT, aT0, aT1);
    ADD2(bS, bS0, bS1);  ADD2(bT, bT0, bT1);

    unsigned u0, u1, u2, u3, v0, v1, v2, v3;
    UNPACK2(u0, u1, aS);  UNPACK2(v0, v1, aT);
    UNPACK2(u2, u3, bS);  UNPACK2(v2, v3, bT);

    // partial contributions for this j-quarter -> smem
    redc[(jq * 4 + 0) * 128 + tb] = __uint_as_float(u0) + __uint_as_float(v0);
    redc[(jq * 4 + 1) * 128 + tb] = __uint_as_float(u1) + __uint_as_float(v1);
    redc[(jq * 4 + 2) * 128 + tb] = __uint_as_float(u2) + __uint_as_float(v2);
    redc[(jq * 4 + 3) * 128 + tb] = __uint_as_float(u3) + __uint_as_float(v3);
    __syncthreads();

    // ------------- tail: all 512 threads; thread = (ii = jq, b = tb) --------
    float mres, sres;
    {
        const int ii = jq;   // target-node index this thread finalizes
        float c = (redc[(0 * 4 + ii) * 128 + tb] + redc[(1 * 4 + ii) * 128 + tb]) +
                  (redc[(2 * 4 + ii) * 128 + tb] + redc[(3 * 4 + ii) * 128 + tb]);
        float base = 0.0f;
#pragma unroll
        for (int w = 0; w < 8; w++) base += red2[ii * 8 + w];
        c += base;

        // per-node MLP: Linear(1,H) -> ReLU -> Linear(H,2)
        const float2 b2v = __ldg((const float2*)&b2[(i0 + ii) * 2]);
        mres = b2v.x;
        sres = b2v.y;
#pragma unroll
        for (int h = 0; h < HH; h++) {
            const float4 q = mlp[ii * HH + h];
            const float hv = fmaxf(fmaf(c, q.x, q.y), 0.f);
            mres = fmaf(hv, q.z, mres);
            sres = fmaf(hv, q.w, sres);
        }
    }
    __syncthreads();   // redc fully consumed; reuse for m/s staging

    // stage results: redc[ii*128 + tb] = m, redc[512 + ii*128 + tb] = s
    redc[jq * 128 + tb]       = mres;
    redc[512 + jq * 128 + tb] = sres;
    __syncthreads();

    // 128 threads assemble float4 and store coalesced (i0 % 4 == 0)
    if (t < 128) {
        const float4 mv = make_float4(redc[0 * 128 + t], redc[1 * 128 + t],
                                      redc[2 * 128 + t], redc[3 * 128 + t]);
        const float4 sv = make_float4(redc[512 + 0 * 128 + t], redc[512 + 1 * 128 + t],
                                      redc[512 + 2 * 128 + t], redc[512 + 3 * 128 + t]);
        const int b = bbase + t;
        *(float4*)&out[b * NN + i0]           = mv;   // means   (B,N)
        *(float4*)&out[BB * NN + b * NN + i0] = sv;   // log_std (B,N)
    }
}

// ---------------------------------------------------------------------------
extern "C" void kernel_launch(void* const* d_in, const int* in_sizes, int n_in,
                              void* d_out, int out_size) {
    const float* x    = (const float*)d_in[0];
    const float* adj  = (const float*)d_in[1];
    const float* bp   = (const float*)d_in[2];
    const float* w_pw = (const float*)d_in[3];
    const float* b_pw = (const float*)d_in[4];
    const float* W1   = (const float*)d_in[5];
    const float* b1   = (const float*)d_in[6];
    const float* W2   = (const float*)d_in[7];
    const float* b2   = (const float*)d_in[8];
    float* out = (float*)d_out;

    // Opt in to >48 KB dynamic shared memory (host-side, idempotent,
    // not a stream op -> not captured; allocates nothing).
    cudaFuncSetAttribute(pwlseg_kernel,
                         cudaFuncAttributeMaxDynamicSharedMemorySize,
                         SMEM_TOTAL);

    dim3 tgrid(8, 8, 2), tblk(32, 8);
    prep_kernel<<<tgrid, tblk>>>(x, adj, bp);

    pwlseg_kernel<<<128, 512, SMEM_TOTAL>>>(bp, w_pw, b_pw, W1, b1, W2, b2, out);
}